// round 7
// baseline (speedup 1.0000x reference)
#include <cuda_runtime.h>
#include <cuda_bf16.h>
#include <cstdint>

// ---------------- problem constants ----------------
#define NB    16
#define DIM   512
#define QKC   512
#define OC    1536          // 2*QK + DIM
#define HW    3136          // 56*56
#define WIDTH 56
#define HEADS 8
#define HD    64
#define NWIN  7
#define P2    49
#define W2    64
#define TOPK  4
#define SCALE 0.04419417382415922f   // 512^-0.5

// ---------------- scratch (static device, no allocs) ----------------
__device__ float g_qkv [ (size_t)NB * OC * HW ];   // 308 MB
__device__ float g_qwin[ NB * P2 * QKC ];
__device__ float g_kwin[ NB * P2 * QKC ];
__device__ int   g_ridx[ NB * P2 * TOPK ];

// ====================================================================
// K1: qkv = w_qkv @ x (+bias)   per batch:  [1536,512] x [512,3136]
// 256(o) x 64(s) tile, BK=16, 256 threads, 8x8 micro-tile,
// double-buffered smem with register prefetch.
// ====================================================================
#define MT 256
#define NT 64
#define KT 16

__global__ __launch_bounds__(256) void qkv_gemm_kernel(
    const float* __restrict__ x, const float* __restrict__ w,
    const float* __restrict__ bias)
{
    const int n  = blockIdx.z;
    const int s0 = blockIdx.x * NT;   // pixel tile  (49 tiles, exact)
    const int o0 = blockIdx.y * MT;   // out-channel tile (6 tiles, exact)
    const int tid = threadIdx.x;
    const int tx = tid & 7;           // s sub-tile (x8)
    const int ty = tid >> 3;          // o sub-tile (x8), 0..31

    __shared__ float As[2][KT][260];  // [k][o]  (+4 pad)
    __shared__ float Bs[2][KT][68];   // [k][s]  (+4 pad)

    const float* xB = x + (size_t)n * (DIM * HW) + s0;
    const float* wB = w + (size_t)o0 * DIM;

    // A (w) loads: 256 o-rows x 16 k = 1024 float4; thread does rows
    // o_a, o_a+64, o_a+128, o_a+192 at k-quad kq.
    const int o_a = tid >> 2;           // 0..63
    const int kq  = (tid & 3) * 4;      // 0,4,8,12
    // B (x) loads: 16 k-rows x 64 s = 256 float4; one per thread
    const int kr = tid >> 4;            // 0..15
    const int sc = (tid & 15) * 4;      // 0..60

    float4 a0, a1, a2, a3, b0;

    // prefetch k0 = 0
    a0 = *reinterpret_cast<const float4*>(wB + (size_t)(o_a      ) * DIM + kq);
    a1 = *reinterpret_cast<const float4*>(wB + (size_t)(o_a +  64) * DIM + kq);
    a2 = *reinterpret_cast<const float4*>(wB + (size_t)(o_a + 128) * DIM + kq);
    a3 = *reinterpret_cast<const float4*>(wB + (size_t)(o_a + 192) * DIM + kq);
    b0 = *reinterpret_cast<const float4*>(xB + (size_t)kr * HW + sc);

    // store buf 0 (A transposed to [k][o])
    {
        const float av[4][4] = {{a0.x,a0.y,a0.z,a0.w},{a1.x,a1.y,a1.z,a1.w},
                                {a2.x,a2.y,a2.z,a2.w},{a3.x,a3.y,a3.z,a3.w}};
        #pragma unroll
        for (int r = 0; r < 4; r++)
            #pragma unroll
            for (int j = 0; j < 4; j++)
                As[0][kq + j][o_a + r * 64] = av[r][j];
        *reinterpret_cast<float4*>(&Bs[0][kr][sc]) = b0;
    }
    __syncthreads();

    float acc[8][8] = {};
    int buf = 0;

    for (int k0 = 0; k0 < DIM; k0 += KT) {
        const bool has_next = (k0 + KT) < DIM;
        if (has_next) {
            const int kn = k0 + KT;
            a0 = *reinterpret_cast<const float4*>(wB + (size_t)(o_a      ) * DIM + kn + kq);
            a1 = *reinterpret_cast<const float4*>(wB + (size_t)(o_a +  64) * DIM + kn + kq);
            a2 = *reinterpret_cast<const float4*>(wB + (size_t)(o_a + 128) * DIM + kn + kq);
            a3 = *reinterpret_cast<const float4*>(wB + (size_t)(o_a + 192) * DIM + kn + kq);
            b0 = *reinterpret_cast<const float4*>(xB + (size_t)(kn + kr) * HW + sc);
        }

        #pragma unroll
        for (int kk = 0; kk < KT; kk++) {
            float4 av0 = *reinterpret_cast<const float4*>(&As[buf][kk][ty * 8]);
            float4 av1 = *reinterpret_cast<const float4*>(&As[buf][kk][ty * 8 + 4]);
            float4 bv0 = *reinterpret_cast<const float4*>(&Bs[buf][kk][tx * 8]);
            float4 bv1 = *reinterpret_cast<const float4*>(&Bs[buf][kk][tx * 8 + 4]);
            float ar[8] = {av0.x, av0.y, av0.z, av0.w, av1.x, av1.y, av1.z, av1.w};
            float br[8] = {bv0.x, bv0.y, bv0.z, bv0.w, bv1.x, bv1.y, bv1.z, bv1.w};
            #pragma unroll
            for (int i = 0; i < 8; i++)
                #pragma unroll
                for (int j = 0; j < 8; j++)
                    acc[i][j] = fmaf(ar[i], br[j], acc[i][j]);
        }

        if (has_next) {
            const int nb = buf ^ 1;
            const float av[4][4] = {{a0.x,a0.y,a0.z,a0.w},{a1.x,a1.y,a1.z,a1.w},
                                    {a2.x,a2.y,a2.z,a2.w},{a3.x,a3.y,a3.z,a3.w}};
            #pragma unroll
            for (int r = 0; r < 4; r++)
                #pragma unroll
                for (int j = 0; j < 4; j++)
                    As[nb][kq + j][o_a + r * 64] = av[r][j];
            *reinterpret_cast<float4*>(&Bs[nb][kr][sc]) = b0;
        }
        __syncthreads();
        buf ^= 1;
    }

    float* oB = g_qkv + ((size_t)n * OC + o0) * HW + s0;
    #pragma unroll
    for (int i = 0; i < 8; i++) {
        const float bb = bias[o0 + ty * 8 + i];
        float4 r0, r1;
        r0.x = acc[i][0] + bb; r0.y = acc[i][1] + bb;
        r0.z = acc[i][2] + bb; r0.w = acc[i][3] + bb;
        r1.x = acc[i][4] + bb; r1.y = acc[i][5] + bb;
        r1.z = acc[i][6] + bb; r1.w = acc[i][7] + bb;
        float* orow = oB + (size_t)(ty * 8 + i) * HW + tx * 8;
        *reinterpret_cast<float4*>(orow)     = r0;
        *reinterpret_cast<float4*>(orow + 4) = r1;
    }
}

// ====================================================================
// K2: lepe = depthwise 3x3 (SAME, zero-pad) over v channels (+b_lepe)
// One thread per 4 horizontally-adjacent pixels; float4 store.
// ====================================================================
__global__ __launch_bounds__(256) void lepe_kernel(
    const float* __restrict__ wl, const float* __restrict__ bl,
    float* __restrict__ out)
{
    int idx = blockIdx.x * 256 + threadIdx.x;      // < NB*DIM*784
    const int seg = idx % (HW / 4);                // 784 segments per (n,c)
    const int t   = idx / (HW / 4);
    const int c   = t % DIM;
    const int n   = t / DIM;
    const int hh  = seg / (WIDTH / 4);             // 0..55
    const int w0  = (seg % (WIDTH / 4)) * 4;       // 0,4,...,52

    const float* v  = g_qkv + ((size_t)n * OC + 2 * QKC + c) * HW;
    const float* wk = wl + c * 9;

    float k0 = wk[0], k1 = wk[1], k2 = wk[2];
    float k3 = wk[3], k4 = wk[4], k5 = wk[5];
    float k6 = wk[6], k7 = wk[7], k8 = wk[8];

    const float bb = bl[c];
    float acc[4] = {bb, bb, bb, bb};

    #pragma unroll
    for (int dy = 0; dy < 3; dy++) {
        const int ih = hh + dy - 1;
        if (ih < 0 || ih >= WIDTH) continue;
        const float* row = v + ih * WIDTH;
        float r[6];
        r[0] = (w0 > 0)           ? __ldg(row + w0 - 1) : 0.0f;
        r[1] = __ldg(row + w0);
        r[2] = __ldg(row + w0 + 1);
        r[3] = __ldg(row + w0 + 2);
        r[4] = __ldg(row + w0 + 3);
        r[5] = (w0 + 4 < WIDTH)   ? __ldg(row + w0 + 4) : 0.0f;

        const float ka = (dy == 0) ? k0 : (dy == 1) ? k3 : k6;
        const float kb = (dy == 0) ? k1 : (dy == 1) ? k4 : k7;
        const float kc = (dy == 0) ? k2 : (dy == 1) ? k5 : k8;
        #pragma unroll
        for (int j = 0; j < 4; j++) {
            acc[j] = fmaf(r[j],     ka, acc[j]);
            acc[j] = fmaf(r[j + 1], kb, acc[j]);
            acc[j] = fmaf(r[j + 2], kc, acc[j]);
        }
    }

    float4 res;
    res.x = acc[0]; res.y = acc[1]; res.z = acc[2]; res.w = acc[3];
    *reinterpret_cast<float4*>(
        out + ((size_t)n * DIM + c) * HW + hh * WIDTH + w0) = res;
}

// ====================================================================
// K3: window means of q (ch 0..511) and k (ch 512..1023)
// ====================================================================
__global__ __launch_bounds__(256) void winmean_kernel()
{
    int idx = blockIdx.x * 256 + threadIdx.x;            // < 16*49*1024
    int c2 = idx & 1023;
    int t  = idx >> 10;
    int p  = t % P2;
    int n  = t / P2;
    int wi = p / NWIN, wj = p % NWIN;
    const float* src = g_qkv + ((size_t)n * OC + c2) * HW + (wi * 8) * WIDTH + wj * 8;
    float s = 0.f;
    #pragma unroll
    for (int y = 0; y < 8; y++)
        #pragma unroll
        for (int x = 0; x < 8; x++)
            s += src[y * WIDTH + x];
    s *= (1.0f / 64.0f);
    if (c2 < QKC) g_qwin[((size_t)n * P2 + p) * QKC + c2]       = s;
    else          g_kwin[((size_t)n * P2 + p) * QKC + c2 - QKC] = s;
}

// ====================================================================
// K4: routing — per (n,p): 49 dots of length 512, top-4 index set.
// (r_weight in the reference is dead code; softmax over gathered keys
//  is permutation-invariant, so only the index set matters.)
// ====================================================================
__global__ __launch_bounds__(64) void route_kernel()
{
    const int p = blockIdx.x, n = blockIdx.y;
    const int tid = threadIdx.x;
    __shared__ float qs[QKC];
    __shared__ float logits[P2];

    const float* qrow = g_qwin + ((size_t)n * P2 + p) * QKC;
    for (int i = tid; i < QKC; i += 64) qs[i] = qrow[i];
    __syncthreads();

    if (tid < P2) {
        const float* kr = g_kwin + ((size_t)n * P2 + tid) * QKC;
        float d = 0.f;
        #pragma unroll 8
        for (int i = 0; i < QKC; i++) d = fmaf(qs[i], kr[i], d);
        logits[tid] = d;          // positive scale doesn't change argmax order
    }
    __syncthreads();

    if (tid == 0) {
        int* rp = g_ridx + ((size_t)n * P2 + p) * TOPK;
        bool used[P2];
        #pragma unroll
        for (int m = 0; m < P2; m++) used[m] = false;
        for (int t = 0; t < TOPK; t++) {
            float best = -1e30f; int bi = 0;
            for (int m = 0; m < P2; m++)
                if (!used[m] && logits[m] > best) { best = logits[m]; bi = m; }
            used[bi] = true;
            rp[t] = bi;
        }
    }
}

// ====================================================================
// K5: pixel attention per (head, p, n).
// S = (scale*Q) K^T (64x256) in smem, softmax, O = P V, out += O.
// ====================================================================
#define SQ_STRIDE 68
#define SS_STRIDE 260
#define SMEM_Q  (64 * SQ_STRIDE)
#define SMEM_KV (64 * SQ_STRIDE)
#define SMEM_S  (64 * SS_STRIDE)
#define ATTN_SMEM_FLOATS (SMEM_Q + SMEM_KV + SMEM_S + 64)

__global__ __launch_bounds__(256) void attn_kernel(float* __restrict__ out)
{
    extern __shared__ float sm[];
    float* Qs   = sm;                    // [d][q]  stride 68, pre-scaled
    float* KVs  = Qs + SMEM_Q;           // K: [d][k] ; later V: [k][d]
    float* Ss   = KVs + SMEM_KV;         // [q][k]  stride 260
    float* rinv = Ss + SMEM_S;           // [64] row inv-sums

    const int h = blockIdx.x, p = blockIdx.y, n = blockIdx.z;
    const int tid = threadIdx.x;
    const int wi = p / NWIN, wj = p % NWIN;
    const int off_p = (wi * 8) * WIDTH + wj * 8;

    const float* qbase = g_qkv + ((size_t)n * OC + (size_t)h * HD) * HW;
    const float* kbase = qbase + (size_t)QKC * HW;
    const float* vbase = qbase + (size_t)(2 * QKC) * HW;

    // load Q -> Qs[d][q], folding in the softmax scale
    #pragma unroll
    for (int i = 0; i < 16; i++) {
        int idx = tid + i * 256;
        int d = idx >> 6, qp = idx & 63;
        Qs[d * SQ_STRIDE + qp] =
            qbase[(size_t)d * HW + off_p + (qp >> 3) * WIDTH + (qp & 7)] * SCALE;
    }

    int widx[TOPK];
    {
        const int* rp = g_ridx + ((size_t)n * P2 + p) * TOPK;
        #pragma unroll
        for (int t = 0; t < TOPK; t++) widx[t] = rp[t];
    }

    const int ty = tid >> 4, tx = tid & 15;

    // ---- S = (scale*Q) K^T, window by window ----
    for (int t = 0; t < TOPK; t++) {
        const int m = widx[t];
        const int off_m = ((m / NWIN) * 8) * WIDTH + (m % NWIN) * 8;
        __syncthreads();
        #pragma unroll
        for (int i = 0; i < 16; i++) {
            int idx = tid + i * 256;
            int d = idx >> 6, kp = idx & 63;
            KVs[d * SQ_STRIDE + kp] =
                kbase[(size_t)d * HW + off_m + (kp >> 3) * WIDTH + (kp & 7)];
        }
        __syncthreads();
        float acc[4][4] = {};
        #pragma unroll
        for (int d = 0; d < 64; d++) {
            float4 qv = *reinterpret_cast<const float4*>(&Qs[d * SQ_STRIDE + ty * 4]);
            float4 kv = *reinterpret_cast<const float4*>(&KVs[d * SQ_STRIDE + tx * 4]);
            float qr[4] = {qv.x, qv.y, qv.z, qv.w};
            float kr[4] = {kv.x, kv.y, kv.z, kv.w};
            #pragma unroll
            for (int i = 0; i < 4; i++)
                #pragma unroll
                for (int j = 0; j < 4; j++)
                    acc[i][j] = fmaf(qr[i], kr[j], acc[i][j]);
        }
        #pragma unroll
        for (int i = 0; i < 4; i++) {
            float4 r;
            r.x = acc[i][0]; r.y = acc[i][1]; r.z = acc[i][2]; r.w = acc[i][3];
            *reinterpret_cast<float4*>(
                &Ss[(ty * 4 + i) * SS_STRIDE + t * 64 + tx * 4]) = r;
        }
    }
    __syncthreads();

    // ---- softmax rows: store exp(x-max), keep 1/sum ----
    {
        const int warp = tid >> 5, lane = tid & 31;
        #pragma unroll
        for (int r = 0; r < 8; r++) {
            const int q = warp * 8 + r;
            float* row = Ss + q * SS_STRIDE;
            float mx = -1e30f;
            #pragma unroll
            for (int k = lane; k < 256; k += 32) mx = fmaxf(mx, row[k]);
            #pragma unroll
            for (int o = 16; o; o >>= 1) mx = fmaxf(mx, __shfl_xor_sync(0xffffffffu, mx, o));
            float s = 0.f;
            #pragma unroll
            for (int k = lane; k < 256; k += 32) {
                float e = __expf(row[k] - mx);
                row[k] = e;
                s += e;
            }
            #pragma unroll
            for (int o = 16; o; o >>= 1) s += __shfl_xor_sync(0xffffffffu, s, o);
            if (lane == 0) rinv[q] = 1.0f / s;
        }
    }

    // ---- O = P V  (kk tiled by 4; Ss rows read as float4) ----
    float oacc[4][4] = {};
    for (int t = 0; t < TOPK; t++) {
        const int m = widx[t];
        const int off_m = ((m / NWIN) * 8) * WIDTH + (m % NWIN) * 8;
        __syncthreads();
        #pragma unroll
        for (int i = 0; i < 16; i++) {
            int idx = tid + i * 256;
            int d = idx >> 6, kp = idx & 63;       // coalesced gmem; transposed STS
            KVs[kp * SQ_STRIDE + d] =
                vbase[(size_t)d * HW + off_m + (kp >> 3) * WIDTH + (kp & 7)];
        }
        __syncthreads();
        #pragma unroll 4
        for (int kk = 0; kk < 64; kk += 4) {
            float pr[4][4];
            #pragma unroll
            for (int i = 0; i < 4; i++) {
                float4 pv = *reinterpret_cast<const float4*>(
                    &Ss[(ty * 4 + i) * SS_STRIDE + t * 64 + kk]);
                pr[i][0] = pv.x; pr[i][1] = pv.y; pr[i][2] = pv.z; pr[i][3] = pv.w;
            }
            #pragma unroll
            for (int u = 0; u < 4; u++) {
                float4 vv = *reinterpret_cast<const float4*>(
                    &KVs[(kk + u) * SQ_STRIDE + tx * 4]);
                float vr[4] = {vv.x, vv.y, vv.z, vv.w};
                #pragma unroll
                for (int i = 0; i < 4; i++)
                    #pragma unroll
                    for (int j = 0; j < 4; j++)
                        oacc[i][j] = fmaf(pr[i][u], vr[j], oacc[i][j]);
            }
        }
    }

    // ---- out += O / rowsum (lepe already in out) ----
    float* obase = out + ((size_t)n * DIM + (size_t)h * HD) * HW + off_p;
    #pragma unroll
    for (int i = 0; i < 4; i++) {
        const int q = ty * 4 + i;
        const float inv = rinv[q];
        const int qoff = (q >> 3) * WIDTH + (q & 7);
        #pragma unroll
        for (int j = 0; j < 4; j++) {
            float* a = obase + (size_t)(tx * 4 + j) * HW + qoff;
            *a += oacc[i][j] * inv;
        }
    }
}

// ====================================================================
extern "C" void kernel_launch(void* const* d_in, const int* in_sizes, int n_in,
                              void* d_out, int out_size)
{
    (void)in_sizes; (void)n_in; (void)out_size;
    const float* x      = (const float*)d_in[0];
    const float* w_qkv  = (const float*)d_in[1];
    const float* b_qkv  = (const float*)d_in[2];
    const float* w_lepe = (const float*)d_in[3];
    const float* b_lepe = (const float*)d_in[4];
    float* out = (float*)d_out;

    // K1: qkv GEMM
    dim3 g1(HW / NT, OC / MT, NB);
    qkv_gemm_kernel<<<g1, 256>>>(x, w_qkv, b_qkv);

    // K2: lepe -> out  (4 px / thread)
    {
        int total = NB * DIM * (HW / 4);           // 6.42M threads
        lepe_kernel<<<total / 256, 256>>>(w_lepe, b_lepe, out);
    }

    // K3: window means
    {
        int total = NB * P2 * 1024;
        winmean_kernel<<<total / 256, 256>>>();
    }

    // K4: routing
    route_kernel<<<dim3(P2, NB), 64>>>();

    // K5: attention (needs >48KB dynamic smem; unconditional attribute set —
    // idempotent, no static guards per harness rules)
    {
        size_t smem = ATTN_SMEM_FLOATS * sizeof(float);
        cudaFuncSetAttribute(attn_kernel,
                             cudaFuncAttributeMaxDynamicSharedMemorySize,
                             (int)smem);
        attn_kernel<<<dim3(HEADS, P2, NB), 256, smem>>>(out);
    }
}

// round 14
// speedup vs baseline: 1.7338x; 1.7338x over previous
#include <cuda_runtime.h>
#include <cuda_bf16.h>
#include <cstdint>
#include <cstring>

// ---------------- problem constants ----------------
#define NB    16
#define DIM   512
#define QKC   512
#define OC    1536          // 2*QK + DIM
#define HW    3136          // 56*56
#define WIDTH 56
#define HEADS 8
#define HD    64
#define NWIN  7
#define P2    49
#define W2    64
#define TOPK  4
#define SCALE 0.04419417382415922f   // 512^-0.5

// ---------------- scratch (static device, no allocs) ----------------
__device__ float g_qkv [ (size_t)NB * OC * HW ];   // 308 MB
__device__ float g_qwin[ NB * P2 * QKC ];
__device__ float g_kwin[ NB * P2 * QKC ];
__device__ int   g_ridx[ NB * P2 * TOPK ];

// ====================================================================
// K1: qkv = w_qkv @ x (+bias) via mma.sync bf16 with split-bf16 inputs.
// a*b ~= ah*bh + ah*bl + al*bh  (al*bl dropped, ~2^-16 relative)
// Block: 128(o) x 64(s), k-chunk 32. 8 warps, warp tile 32x32
// (2 m-tiles x 4 n-tiles of m16n8k16).
// ====================================================================
#define GM 128
#define GN 64
#define GK 32
#define APAD 40   // bf16 per smem row (80 B) — conflict-free fragment reads

__device__ __forceinline__ void split1(float v, unsigned short& h, unsigned short& l)
{
    __nv_bfloat16 hb = __float2bfloat16_rn(v);
    float r = v - __bfloat162float(hb);
    __nv_bfloat16 lb = __float2bfloat16_rn(r);
    memcpy(&h, &hb, 2); memcpy(&l, &lb, 2);
}

__device__ __forceinline__ void split2(float a, float b, uint32_t& hi, uint32_t& lo)
{
    unsigned short ha, la, hb, lb;
    split1(a, ha, la); split1(b, hb, lb);
    hi = (uint32_t)ha | ((uint32_t)hb << 16);   // low half = first elem
    lo = (uint32_t)la | ((uint32_t)lb << 16);
}

__device__ __forceinline__ void mma_bf16(float* c, const uint32_t* a,
                                         uint32_t b0, uint32_t b1)
{
    asm volatile(
        "mma.sync.aligned.m16n8k16.row.col.f32.bf16.bf16.f32 "
        "{%0,%1,%2,%3}, {%4,%5,%6,%7}, {%8,%9}, {%0,%1,%2,%3};\n"
        : "+f"(c[0]), "+f"(c[1]), "+f"(c[2]), "+f"(c[3])
        : "r"(a[0]), "r"(a[1]), "r"(a[2]), "r"(a[3]), "r"(b0), "r"(b1));
}

__global__ __launch_bounds__(256) void qkv_mma_kernel(
    const float* __restrict__ x, const float* __restrict__ w,
    const float* __restrict__ bias, int n_base)
{
    const int n  = n_base + blockIdx.z;
    const int s0 = blockIdx.x * GN;
    const int o0 = blockIdx.y * GM;
    const int tid  = threadIdx.x;
    const int warp = tid >> 5, lane = tid & 31;
    const int g = lane >> 2, t = lane & 3;
    const int wm = warp >> 1, wn = warp & 1;

    __shared__ __nv_bfloat16 sAh[GM][APAD], sAl[GM][APAD];
    __shared__ __nv_bfloat16 sBh[GN][APAD], sBl[GN][APAD];

    float c[2][4][4] = {};

    const float* xB = x + (size_t)n * DIM * HW;

    for (int k0 = 0; k0 < DIM; k0 += GK) {
        __syncthreads();   // prev iter's readers done before overwrite
        // ---- A tile: w rows o0..o0+127, cols k0..k0+31 (fp32 -> hi/lo) ----
        {
            const int ra = tid >> 1;            // 0..127
            const int kc = (tid & 1) * 16;      // 0 or 16
            const float* src = w + (size_t)(o0 + ra) * DIM + k0 + kc;
            #pragma unroll
            for (int q = 0; q < 4; q++) {
                float4 v = *reinterpret_cast<const float4*>(src + q * 4);
                uint32_t h0, l0, h1, l1;
                split2(v.x, v.y, h0, l0);
                split2(v.z, v.w, h1, l1);
                *reinterpret_cast<uint32_t*>(&sAh[ra][kc + q * 4])     = h0;
                *reinterpret_cast<uint32_t*>(&sAh[ra][kc + q * 4 + 2]) = h1;
                *reinterpret_cast<uint32_t*>(&sAl[ra][kc + q * 4])     = l0;
                *reinterpret_cast<uint32_t*>(&sAl[ra][kc + q * 4 + 2]) = l1;
            }
        }
        // ---- B tile: x rows k0..k0+31, cols s0..s0+63 -> transposed [s][k] ----
        {
            const int kb = tid >> 3;            // 0..31
            const int sc = (tid & 7) * 8;       // 0..56
            const float* src = xB + (size_t)(k0 + kb) * HW + s0 + sc;
            #pragma unroll
            for (int q = 0; q < 2; q++) {
                float4 v = *reinterpret_cast<const float4*>(src + q * 4);
                float vv[4] = {v.x, v.y, v.z, v.w};
                #pragma unroll
                for (int e = 0; e < 4; e++) {
                    unsigned short h, l;
                    split1(vv[e], h, l);
                    const int srow = sc + q * 4 + e;
                    *reinterpret_cast<unsigned short*>(&sBh[srow][kb]) = h;
                    *reinterpret_cast<unsigned short*>(&sBl[srow][kb]) = l;
                }
            }
        }
        __syncthreads();

        // ---- compute: 2 k16 steps ----
        #pragma unroll
        for (int ks = 0; ks < 2; ks++) {
            const int ko = ks * 16;
            uint32_t ah[2][4], al[2][4];
            #pragma unroll
            for (int mi = 0; mi < 2; mi++) {
                const int row = wm * 32 + mi * 16 + g;
                ah[mi][0] = *reinterpret_cast<const uint32_t*>(&sAh[row    ][ko + 2 * t]);
                ah[mi][1] = *reinterpret_cast<const uint32_t*>(&sAh[row + 8][ko + 2 * t]);
                ah[mi][2] = *reinterpret_cast<const uint32_t*>(&sAh[row    ][ko + 2 * t + 8]);
                ah[mi][3] = *reinterpret_cast<const uint32_t*>(&sAh[row + 8][ko + 2 * t + 8]);
                al[mi][0] = *reinterpret_cast<const uint32_t*>(&sAl[row    ][ko + 2 * t]);
                al[mi][1] = *reinterpret_cast<const uint32_t*>(&sAl[row + 8][ko + 2 * t]);
                al[mi][2] = *reinterpret_cast<const uint32_t*>(&sAl[row    ][ko + 2 * t + 8]);
                al[mi][3] = *reinterpret_cast<const uint32_t*>(&sAl[row + 8][ko + 2 * t + 8]);
            }
            #pragma unroll
            for (int ni = 0; ni < 4; ni++) {
                const int br = wn * 32 + ni * 8 + g;
                uint32_t bh0 = *reinterpret_cast<const uint32_t*>(&sBh[br][ko + 2 * t]);
                uint32_t bh1 = *reinterpret_cast<const uint32_t*>(&sBh[br][ko + 2 * t + 8]);
                uint32_t bl0 = *reinterpret_cast<const uint32_t*>(&sBl[br][ko + 2 * t]);
                uint32_t bl1 = *reinterpret_cast<const uint32_t*>(&sBl[br][ko + 2 * t + 8]);
                #pragma unroll
                for (int mi = 0; mi < 2; mi++) {
                    mma_bf16(c[mi][ni], ah[mi], bh0, bh1);
                    mma_bf16(c[mi][ni], ah[mi], bl0, bl1);
                    mma_bf16(c[mi][ni], al[mi], bh0, bh1);
                }
            }
        }
    }

    // ---- epilogue: +bias, float2 stores ----
    float* oB = g_qkv + ((size_t)n * OC + o0) * HW + s0;
    #pragma unroll
    for (int mi = 0; mi < 2; mi++) {
        const int orow = wm * 32 + mi * 16 + g;
        const float bv0 = bias[o0 + orow];
        const float bv1 = bias[o0 + orow + 8];
        #pragma unroll
        for (int ni = 0; ni < 4; ni++) {
            const int scol = wn * 32 + ni * 8 + 2 * t;
            float2 p0, p1;
            p0.x = c[mi][ni][0] + bv0; p0.y = c[mi][ni][1] + bv0;
            p1.x = c[mi][ni][2] + bv1; p1.y = c[mi][ni][3] + bv1;
            *reinterpret_cast<float2*>(oB + (size_t)orow * HW + scol) = p0;
            *reinterpret_cast<float2*>(oB + (size_t)(orow + 8) * HW + scol) = p1;
        }
    }
}

// ====================================================================
// K2: lepe = depthwise 3x3 (SAME, zero-pad) over v channels (+b_lepe)
// ====================================================================
__global__ __launch_bounds__(256) void lepe_kernel(
    const float* __restrict__ wl, const float* __restrict__ bl,
    float* __restrict__ out)
{
    int idx = blockIdx.x * 256 + threadIdx.x;      // < NB*DIM*784
    const int seg = idx % (HW / 4);
    const int t   = idx / (HW / 4);
    const int c   = t % DIM;
    const int n   = t / DIM;
    const int hh  = seg / (WIDTH / 4);
    const int w0  = (seg % (WIDTH / 4)) * 4;

    const float* v  = g_qkv + ((size_t)n * OC + 2 * QKC + c) * HW;
    const float* wk = wl + c * 9;

    float k0 = wk[0], k1 = wk[1], k2 = wk[2];
    float k3 = wk[3], k4 = wk[4], k5 = wk[5];
    float k6 = wk[6], k7 = wk[7], k8 = wk[8];

    const float bb = bl[c];
    float acc[4] = {bb, bb, bb, bb};

    #pragma unroll
    for (int dy = 0; dy < 3; dy++) {
        const int ih = hh + dy - 1;
        if (ih < 0 || ih >= WIDTH) continue;
        const float* row = v + ih * WIDTH;
        float r[6];
        r[0] = (w0 > 0)           ? __ldg(row + w0 - 1) : 0.0f;
        r[1] = __ldg(row + w0);
        r[2] = __ldg(row + w0 + 1);
        r[3] = __ldg(row + w0 + 2);
        r[4] = __ldg(row + w0 + 3);
        r[5] = (w0 + 4 < WIDTH)   ? __ldg(row + w0 + 4) : 0.0f;

        const float ka = (dy == 0) ? k0 : (dy == 1) ? k3 : k6;
        const float kb = (dy == 0) ? k1 : (dy == 1) ? k4 : k7;
        const float kc = (dy == 0) ? k2 : (dy == 1) ? k5 : k8;
        #pragma unroll
        for (int j = 0; j < 4; j++) {
            acc[j] = fmaf(r[j],     ka, acc[j]);
            acc[j] = fmaf(r[j + 1], kb, acc[j]);
            acc[j] = fmaf(r[j + 2], kc, acc[j]);
        }
    }

    float4 res;
    res.x = acc[0]; res.y = acc[1]; res.z = acc[2]; res.w = acc[3];
    *reinterpret_cast<float4*>(
        out + ((size_t)n * DIM + c) * HW + hh * WIDTH + w0) = res;
}

// ====================================================================
// K3: window means of q (ch 0..511) and k (ch 512..1023)
// ====================================================================
__global__ __launch_bounds__(256) void winmean_kernel()
{
    int idx = blockIdx.x * 256 + threadIdx.x;            // < 16*49*1024
    int c2 = idx & 1023;
    int t  = idx >> 10;
    int p  = t % P2;
    int n  = t / P2;
    int wi = p / NWIN, wj = p % NWIN;
    const float* src = g_qkv + ((size_t)n * OC + c2) * HW + (wi * 8) * WIDTH + wj * 8;
    float s = 0.f;
    #pragma unroll
    for (int y = 0; y < 8; y++)
        #pragma unroll
        for (int x = 0; x < 8; x++)
            s += src[y * WIDTH + x];
    s *= (1.0f / 64.0f);
    if (c2 < QKC) g_qwin[((size_t)n * P2 + p) * QKC + c2]       = s;
    else          g_kwin[((size_t)n * P2 + p) * QKC + c2 - QKC] = s;
}

// ====================================================================
// K4: routing — warp-parallel dots + warp-parallel top-4 argmax.
// (r_weight in the reference is dead code; only the index set matters.)
// ====================================================================
__global__ __launch_bounds__(256) void route_kernel()
{
    const int p = blockIdx.x, n = blockIdx.y;
    const int tid  = threadIdx.x;
    const int warp = tid >> 5, lane = tid & 31;
    __shared__ float qs[QKC];
    __shared__ float logits[64];           // 49 used, rest = -inf

    const float* qrow = g_qwin + ((size_t)n * P2 + p) * QKC;
    for (int i = tid; i < QKC; i += 256) qs[i] = qrow[i];
    if (tid < 64 - P2) logits[P2 + tid] = -1e30f;
    __syncthreads();

    for (int m = warp; m < P2; m += 8) {
        const float* kr = g_kwin + ((size_t)n * P2 + m) * QKC;
        float d = 0.f;
        #pragma unroll
        for (int i = 0; i < QKC / 32; i++)
            d = fmaf(qs[lane + i * 32], kr[lane + i * 32], d);
        #pragma unroll
        for (int o = 16; o; o >>= 1) d += __shfl_xor_sync(0xffffffffu, d, o);
        if (lane == 0) logits[m] = d;
    }
    __syncthreads();

    if (warp == 0) {
        float v0 = logits[lane];
        float v1 = logits[lane + 32];
        int* rp = g_ridx + ((size_t)n * P2 + p) * TOPK;
        #pragma unroll
        for (int t = 0; t < TOPK; t++) {
            float bv; int bi;
            if (v0 >= v1) { bv = v0; bi = lane; }
            else          { bv = v1; bi = lane + 32; }
            #pragma unroll
            for (int o = 16; o; o >>= 1) {
                float ov = __shfl_xor_sync(0xffffffffu, bv, o);
                int   oi = __shfl_xor_sync(0xffffffffu, bi, o);
                if (ov > bv || (ov == bv && oi < bi)) { bv = ov; bi = oi; }
            }
            if (lane == 0) rp[t] = bi;
            if (bi == lane)      v0 = -1e30f;
            if (bi == lane + 32) v1 = -1e30f;
        }
    }
}

// ====================================================================
// K5: pixel attention per (head, p, n).
// ====================================================================
#define SQ_STRIDE 68
#define SS_STRIDE 260
#define SMEM_Q  (64 * SQ_STRIDE)
#define SMEM_KV (64 * SQ_STRIDE)
#define SMEM_S  (64 * SS_STRIDE)
#define ATTN_SMEM_FLOATS (SMEM_Q + SMEM_KV + SMEM_S + 64)

__global__ __launch_bounds__(256) void attn_kernel(float* __restrict__ out)
{
    extern __shared__ float sm[];
    float* Qs   = sm;
    float* KVs  = Qs + SMEM_Q;
    float* Ss   = KVs + SMEM_KV;
    float* rinv = Ss + SMEM_S;

    const int h = blockIdx.x, p = blockIdx.y, n = blockIdx.z;
    const int tid = threadIdx.x;
    const int wi = p / NWIN, wj = p % NWIN;
    const int off_p = (wi * 8) * WIDTH + wj * 8;

    const float* qbase = g_qkv + ((size_t)n * OC + (size_t)h * HD) * HW;
    const float* kbase = qbase + (size_t)QKC * HW;
    const float* vbase = qbase + (size_t)(2 * QKC) * HW;

    #pragma unroll
    for (int i = 0; i < 16; i++) {
        int idx = tid + i * 256;
        int d = idx >> 6, qp = idx & 63;
        Qs[d * SQ_STRIDE + qp] =
            qbase[(size_t)d * HW + off_p + (qp >> 3) * WIDTH + (qp & 7)] * SCALE;
    }

    int widx[TOPK];
    {
        const int* rp = g_ridx + ((size_t)n * P2 + p) * TOPK;
        #pragma unroll
        for (int t = 0; t < TOPK; t++) widx[t] = rp[t];
    }

    const int ty = tid >> 4, tx = tid & 15;

    for (int t = 0; t < TOPK; t++) {
        const int m = widx[t];
        const int off_m = ((m / NWIN) * 8) * WIDTH + (m % NWIN) * 8;
        __syncthreads();
        #pragma unroll
        for (int i = 0; i < 16; i++) {
            int idx = tid + i * 256;
            int d = idx >> 6, kp = idx & 63;
            KVs[d * SQ_STRIDE + kp] =
                kbase[(size_t)d * HW + off_m + (kp >> 3) * WIDTH + (kp & 7)];
        }
        __syncthreads();
        float acc[4][4] = {};
        #pragma unroll
        for (int d = 0; d < 64; d++) {
            float4 qv = *reinterpret_cast<const float4*>(&Qs[d * SQ_STRIDE + ty * 4]);
            float4 kv = *reinterpret_cast<const float4*>(&KVs[d * SQ_STRIDE + tx * 4]);
            float qr[4] = {qv.x, qv.y, qv.z, qv.w};
            float kr[4] = {kv.x, kv.y, kv.z, kv.w};
            #pragma unroll
            for (int i = 0; i < 4; i++)
                #pragma unroll
                for (int j = 0; j < 4; j++)
                    acc[i][j] = fmaf(qr[i], kr[j], acc[i][j]);
        }
        #pragma unroll
        for (int i = 0; i < 4; i++) {
            float4 r;
            r.x = acc[i][0]; r.y = acc[i][1]; r.z = acc[i][2]; r.w = acc[i][3];
            *reinterpret_cast<float4*>(
                &Ss[(ty * 4 + i) * SS_STRIDE + t * 64 + tx * 4]) = r;
        }
    }
    __syncthreads();

    {
        const int warp = tid >> 5, lane = tid & 31;
        #pragma unroll
        for (int r = 0; r < 8; r++) {
            const int q = warp * 8 + r;
            float* row = Ss + q * SS_STRIDE;
            float mx = -1e30f;
            #pragma unroll
            for (int k = lane; k < 256; k += 32) mx = fmaxf(mx, row[k]);
            #pragma unroll
            for (int o = 16; o; o >>= 1) mx = fmaxf(mx, __shfl_xor_sync(0xffffffffu, mx, o));
            float s = 0.f;
            #pragma unroll
            for (int k = lane; k < 256; k += 32) {
                float e = __expf(row[k] - mx);
                row[k] = e;
                s += e;
            }
            #pragma unroll
            for (int o = 16; o; o >>= 1) s += __shfl_xor_sync(0xffffffffu, s, o);
            if (lane == 0) rinv[q] = 1.0f / s;
        }
    }

    float oacc[4][4] = {};
    for (int t = 0; t < TOPK; t++) {
        const int m = widx[t];
        const int off_m = ((m / NWIN) * 8) * WIDTH + (m % NWIN) * 8;
        __syncthreads();
        #pragma unroll
        for (int i = 0; i < 16; i++) {
            int idx = tid + i * 256;
            int d = idx >> 6, kp = idx & 63;
            KVs[kp * SQ_STRIDE + d] =
                vbase[(size_t)d * HW + off_m + (kp >> 3) * WIDTH + (kp & 7)];
        }
        __syncthreads();
        #pragma unroll 4
        for (int kk = 0; kk < 64; kk += 4) {
            float pr[4][4];
            #pragma unroll
            for (int i = 0; i < 4; i++) {
                float4 pv = *reinterpret_cast<const float4*>(
                    &Ss[(ty * 4 + i) * SS_STRIDE + t * 64 + kk]);
                pr[i][0] = pv.x; pr[i][1] = pv.y; pr[i][2] = pv.z; pr[i][3] = pv.w;
            }
            #pragma unroll
            for (int u = 0; u < 4; u++) {
                float4 vv = *reinterpret_cast<const float4*>(
                    &KVs[(kk + u) * SQ_STRIDE + tx * 4]);
                float vr[4] = {vv.x, vv.y, vv.z, vv.w};
                #pragma unroll
                for (int i = 0; i < 4; i++)
                    #pragma unroll
                    for (int j = 0; j < 4; j++)
                        oacc[i][j] = fmaf(pr[i][u], vr[j], oacc[i][j]);
            }
        }
    }

    float* obase = out + ((size_t)n * DIM + (size_t)h * HD) * HW + off_p;
    #pragma unroll
    for (int i = 0; i < 4; i++) {
        const int q = ty * 4 + i;
        const float inv = rinv[q];
        const int qoff = (q >> 3) * WIDTH + (q & 7);
        #pragma unroll
        for (int j = 0; j < 4; j++) {
            float* a = obase + (size_t)(tx * 4 + j) * HW + qoff;
            *a += oacc[i][j] * inv;
        }
    }
}

// ====================================================================
extern "C" void kernel_launch(void* const* d_in, const int* in_sizes, int n_in,
                              void* d_out, int out_size)
{
    (void)in_sizes; (void)n_in; (void)out_size;
    const float* x      = (const float*)d_in[0];
    const float* w_qkv  = (const float*)d_in[1];
    const float* b_qkv  = (const float*)d_in[2];
    const float* w_lepe = (const float*)d_in[3];
    const float* b_lepe = (const float*)d_in[4];
    float* out = (float*)d_out;

    // K1: qkv GEMM (tensor cores) — 4 launches so ncu -s 5 profiles one
    dim3 g1(HW / GN, OC / GM, 4);
    qkv_mma_kernel<<<g1, 256>>>(x, w_qkv, b_qkv, 0);
    qkv_mma_kernel<<<g1, 256>>>(x, w_qkv, b_qkv, 4);
    qkv_mma_kernel<<<g1, 256>>>(x, w_qkv, b_qkv, 8);
    qkv_mma_kernel<<<g1, 256>>>(x, w_qkv, b_qkv, 12);

    // K2: lepe -> out  (4 px / thread)
    {
        int total = NB * DIM * (HW / 4);
        lepe_kernel<<<total / 256, 256>>>(w_lepe, b_lepe, out);
    }

    // K3: window means
    {
        int total = NB * P2 * 1024;
        winmean_kernel<<<total / 256, 256>>>();
    }

    // K4: routing (warp-parallel)
    route_kernel<<<dim3(P2, NB), 256>>>();

    // K5: attention
    {
        size_t smem = ATTN_SMEM_FLOATS * sizeof(float);
        cudaFuncSetAttribute(attn_kernel,
                             cudaFuncAttributeMaxDynamicSharedMemorySize,
                             (int)smem);
        attn_kernel<<<dim3(HEADS, P2, NB), 256, smem>>>(out);
    }
}